// round 3
// baseline (speedup 1.0000x reference)
#include <cuda_runtime.h>
#include <cstdint>

// TemplatePointwiseAttention, fully fused, fp32 with packed f32x2 FMA.
//
// Per CTA: 64 pixels.  Stages (shared-memory resident, one kernel):
//   0) stage weights (96KB), z-tile (transposed), t-tile into shared
//   1) Q = Z @ Wq * 0.25                      (register-tiled GEMM, f32x2)
//   2) per (pixel,head): qk = Wk_h^T q_h ; logits = qk . t_s + bias ;
//      softmax over S=4 ; tbar = sum_s a_s t_s ; o_h = tbar @ Wv_h
//   3) Out = O @ Wo + bo, gated by (sum(mask)>0)  (register-tiled GEMM)
//
// No global intermediates: HBM traffic = t + z + out = 512 MB (floor).

typedef unsigned long long u64;

#define NCTA 4096      // (512*512)/64
#define PT   64        // pixels per CTA

// shared layout (float offsets); all even -> 8B alignment for u64 LDS/STS
#define OFF_ZS 0       // [128][65] z transposed; reused as OS[64][66] after ph1
#define OFF_TS 8320    // [4][64][65]
#define OFF_QS 24960   // [64][66]
#define OFF_WQ 29184   // [128][64]
#define OFF_WK 37376   // [64][64]
#define OFF_WV 41472   // [64][64]
#define OFF_WO 45568   // [64][128]
#define OFF_BO 53760   // [128]
#define SMEM_FLOATS 53888

__device__ __forceinline__ u64 pk2(float lo, float hi) {
    u64 r; asm("mov.b64 %0, {%1, %2};" : "=l"(r) : "f"(lo), "f"(hi)); return r;
}
__device__ __forceinline__ void upk2(u64 v, float& lo, float& hi) {
    asm("mov.b64 {%0, %1}, %2;" : "=f"(lo), "=f"(hi) : "l"(v));
}
__device__ __forceinline__ u64 ffma2(u64 a, u64 b, u64 c) {
    u64 d; asm("fma.rn.f32x2 %0, %1, %2, %3;" : "=l"(d) : "l"(a), "l"(b), "l"(c)); return d;
}

__global__ void __launch_bounds__(256, 1)
tpa_kernel(const float* __restrict__ t_g, const float* __restrict__ z_g,
           const float* __restrict__ mask_g,
           const float* __restrict__ wq_g, const float* __restrict__ wk_g,
           const float* __restrict__ wv_g, const float* __restrict__ wo_g,
           const float* __restrict__ bo_g, float* __restrict__ out_g)
{
    extern __shared__ float S[];
    const int tid  = threadIdx.x;
    const int base = blockIdx.x * PT;

    // mask -> bias + output gate
    float bias0, bias1, bias2, bias3, msum;
    {
        float m0 = __ldg(mask_g + 0), m1 = __ldg(mask_g + 1);
        float m2 = __ldg(mask_g + 2), m3 = __ldg(mask_g + 3);
        bias0 = 1e9f*(m0-1.f); bias1 = 1e9f*(m1-1.f);
        bias2 = 1e9f*(m2-1.f); bias3 = 1e9f*(m3-1.f);
        msum = m0+m1+m2+m3;
    }
    const float gate = (msum > 0.f) ? 1.f : 0.f;

    // ---------------- phase 0: staging ----------------
    {
        const float4* src; float4* dst;
        src = (const float4*)wq_g; dst = (float4*)(S + OFF_WQ);
        for (int i = tid; i < 2048; i += 256) dst[i] = src[i];
        src = (const float4*)wk_g; dst = (float4*)(S + OFF_WK);
        for (int i = tid; i < 1024; i += 256) dst[i] = src[i];
        src = (const float4*)wv_g; dst = (float4*)(S + OFF_WV);
        for (int i = tid; i < 1024; i += 256) dst[i] = src[i];
        src = (const float4*)wo_g; dst = (float4*)(S + OFF_WO);
        for (int i = tid; i < 2048; i += 256) dst[i] = src[i];
        src = (const float4*)bo_g; dst = (float4*)(S + OFF_BO);
        for (int i = tid; i < 32;   i += 256) dst[i] = src[i];

        // Z tile: global [p][128] -> shared transposed ZS[c][p] (row stride 65)
        for (int i = tid; i < 2048; i += 256) {
            int p = i >> 5, c4 = i & 31;
            float4 v = *(const float4*)(z_g + (size_t)(base + p) * 128 + c4 * 4);
            S[OFF_ZS + (4*c4+0)*65 + p] = v.x;
            S[OFF_ZS + (4*c4+1)*65 + p] = v.y;
            S[OFF_ZS + (4*c4+2)*65 + p] = v.z;
            S[OFF_ZS + (4*c4+3)*65 + p] = v.w;
        }
        // T tile: TS[s][p][c] (row stride 65)
        for (int i = tid; i < 4096; i += 256) {
            int s = i >> 10, p = (i >> 4) & 63, c4 = i & 15;
            float4 v = *(const float4*)(t_g + ((size_t)s << 24) +
                                        (size_t)(base + p) * 64 + c4 * 4);
            float* tr = S + OFF_TS + (s*64 + p)*65 + c4*4;
            tr[0] = v.x; tr[1] = v.y; tr[2] = v.z; tr[3] = v.w;
        }
    }
    __syncthreads();

    // ---------------- phase 1: Q = Z @ Wq * 0.25 -> QS[p][o] (stride 66) ----
    {
        const int og = tid & 15, pg = tid >> 4;
        const int p0 = pg * 4;
        u64 acc[4][2];
#pragma unroll
        for (int i = 0; i < 4; ++i) { acc[i][0] = 0ull; acc[i][1] = 0ull; }
#pragma unroll 4
        for (int c = 0; c < 128; ++c) {
            const float* zr = S + OFF_ZS + c*65 + p0;
            const float* wr = S + OFF_WQ + c*64 + 2*og;
            u64 w0 = *(const u64*)(wr);
            u64 w1 = *(const u64*)(wr + 32);
#pragma unroll
            for (int i = 0; i < 4; ++i) {
                u64 zz = pk2(zr[i], zr[i]);
                acc[i][0] = ffma2(zz, w0, acc[i][0]);
                acc[i][1] = ffma2(zz, w1, acc[i][1]);
            }
        }
#pragma unroll
        for (int i = 0; i < 4; ++i) {
            float a0, a1, b0, b1;
            upk2(acc[i][0], a0, a1); upk2(acc[i][1], b0, b1);
            float* q = S + OFF_QS + (p0 + i) * 66;
            q[2*og]    = a0 * 0.25f;  q[2*og+1]  = a1 * 0.25f;
            q[2*og+32] = b0 * 0.25f;  q[2*og+33] = b1 * 0.25f;
        }
    }
    __syncthreads();

    // ---------------- phase 2: attention middle (thread = (head, pixel)) ----
    {
        const int h = tid >> 6, p = tid & 63;
        const float* qrow = S + OFF_QS + p*66 + h*16;
        u64 q2[8];
#pragma unroll
        for (int j = 0; j < 8; ++j) q2[j] = *(const u64*)(qrow + 2*j);

        const float* tsp = S + OFF_TS + p*65;        // + s*4160 + c
        const float* wkh = S + OFF_WK + h*16;
        float lg0 = bias0, lg1 = bias1, lg2 = bias2, lg3 = bias3;
#pragma unroll 2
        for (int c = 0; c < 64; ++c) {
            const float* wr = wkh + c*64;
            u64 a0 = 0ull, a1 = 0ull;
#pragma unroll
            for (int j = 0; j < 8; j += 2) {
                a0 = ffma2(*(const u64*)(wr + 2*j),     q2[j],   a0);
                a1 = ffma2(*(const u64*)(wr + 2*j + 2), q2[j+1], a1);
            }
            float x0, x1, y0, y1; upk2(a0, x0, x1); upk2(a1, y0, y1);
            float qkc = (x0 + x1) + (y0 + y1);
            lg0 += qkc * tsp[c];
            lg1 += qkc * tsp[4160  + c];
            lg2 += qkc * tsp[8320  + c];
            lg3 += qkc * tsp[12480 + c];
        }
        float m  = fmaxf(fmaxf(lg0, lg1), fmaxf(lg2, lg3));
        float e0 = __expf(lg0 - m), e1 = __expf(lg1 - m);
        float e2 = __expf(lg2 - m), e3 = __expf(lg3 - m);
        float inv = 1.f / (e0 + e1 + e2 + e3);
        float aw0 = e0*inv, aw1 = e1*inv, aw2 = e2*inv, aw3 = e3*inv;

        u64 oacc[8];
#pragma unroll
        for (int j = 0; j < 8; ++j) oacc[j] = 0ull;
        const float* wvh = S + OFF_WV + h*16;
#pragma unroll 2
        for (int c = 0; c < 64; ++c) {
            float tb = aw0*tsp[c] + aw1*tsp[4160+c] + aw2*tsp[8320+c] + aw3*tsp[12480+c];
            u64 tb2 = pk2(tb, tb);
            const float* wr = wvh + c*64;
#pragma unroll
            for (int j = 0; j < 8; ++j)
                oacc[j] = ffma2(tb2, *(const u64*)(wr + 2*j), oacc[j]);
        }
        // write O into ZS region (dead after phase 1), OS[p][o], stride 66
        float* osr = S + OFF_ZS + p*66 + h*16;
#pragma unroll
        for (int j = 0; j < 8; ++j) *(u64*)(osr + 2*j) = oacc[j];
    }
    __syncthreads();

    // ---------------- phase 3: Out = O @ Wo + bo, gated ----------------
    {
        const int og = tid & 15, pg = tid >> 4;
        const int p0 = pg * 4;
        u64 acc[4][4];
#pragma unroll
        for (int i = 0; i < 4; ++i)
#pragma unroll
            for (int k = 0; k < 4; ++k) acc[i][k] = 0ull;
#pragma unroll 2
        for (int c = 0; c < 64; ++c) {
            const float* wr = S + OFF_WO + c*128 + 2*og;
            u64 w0 = *(const u64*)(wr);
            u64 w1 = *(const u64*)(wr + 32);
            u64 w2 = *(const u64*)(wr + 64);
            u64 w3 = *(const u64*)(wr + 96);
            const float* osc = S + OFF_ZS + p0*66 + c;
#pragma unroll
            for (int i = 0; i < 4; ++i) {
                float ov = osc[i * 66];
                u64 od = pk2(ov, ov);
                acc[i][0] = ffma2(od, w0, acc[i][0]);
                acc[i][1] = ffma2(od, w1, acc[i][1]);
                acc[i][2] = ffma2(od, w2, acc[i][2]);
                acc[i][3] = ffma2(od, w3, acc[i][3]);
            }
        }
        const float* bo_s = S + OFF_BO;
#pragma unroll
        for (int i = 0; i < 4; ++i) {
            float* orow = out_g + (size_t)(base + p0 + i) * 128;
#pragma unroll
            for (int k = 0; k < 4; ++k) {
                float r0, r1; upk2(acc[i][k], r0, r1);
                int o = 2*og + 32*k;
                r0 = (r0 + bo_s[o])     * gate;
                r1 = (r1 + bo_s[o + 1]) * gate;
                *(u64*)(orow + o) = pk2(r0, r1);
            }
        }
    }
}

extern "C" void kernel_launch(void* const* d_in, const int* in_sizes, int n_in,
                              void* d_out, int out_size)
{
    (void)in_sizes; (void)n_in; (void)out_size;
    const float* t_g  = (const float*)d_in[0];
    const float* z_g  = (const float*)d_in[1];
    const float* mk_g = (const float*)d_in[2];
    const float* wq_g = (const float*)d_in[3];
    const float* wk_g = (const float*)d_in[4];
    const float* wv_g = (const float*)d_in[5];
    const float* wo_g = (const float*)d_in[6];
    const float* bo_g = (const float*)d_in[7];
    float* out_g = (float*)d_out;

    cudaFuncSetAttribute(tpa_kernel, cudaFuncAttributeMaxDynamicSharedMemorySize,
                         SMEM_FLOATS * (int)sizeof(float));
    tpa_kernel<<<NCTA, 256, SMEM_FLOATS * sizeof(float)>>>(
        t_g, z_g, mk_g, wq_g, wk_g, wv_g, wo_g, bo_g, out_g);
}

// round 9
// speedup vs baseline: 1.1402x; 1.1402x over previous
#include <cuda_runtime.h>
#include <cstdint>

// TemplatePointwiseAttention, fully fused, fp32 + packed f32x2 FMA.
// R9 == R7 resubmit (never ran): 512 thr/CTA, TS4[p][c][s] float4 repack
// (1x LDS.128 template reads), conflict-free TS4 staging permutation.

typedef unsigned long long u64;

#define NCTA 4096      // (512*512)/64
#define PT   64        // pixels per CTA
#define NTHR 512

// shared layout (float offsets); all even -> 8B alignment for u64 LDS/STS
#define OFF_ZS 0       // [128][65] z transposed; reused as OS_a[64][66] in ph2
#define OFF_TS 8320    // TS4[64][64][4], row stride 260 (=64*4+4 pad), 16640 fl
#define OFF_QS 24960   // [64][66] Q; reused as logit-partials, then OS_b[64][66]
#define OFF_WQ 29184   // [128][64]
#define OFF_WK 37376   // [64][64]
#define OFF_WV 41472   // [64][64]
#define OFF_WO 45568   // [64][128]
#define OFF_BO 53760   // [128]
#define SMEM_FLOATS 53888
#define TS_PSTRIDE 260

__device__ __forceinline__ u64 pk2(float lo, float hi) {
    u64 r; asm("mov.b64 %0, {%1, %2};" : "=l"(r) : "f"(lo), "f"(hi)); return r;
}
__device__ __forceinline__ void upk2(u64 v, float& lo, float& hi) {
    asm("mov.b64 {%0, %1}, %2;" : "=f"(lo), "=f"(hi) : "l"(v));
}
__device__ __forceinline__ u64 ffma2(u64 a, u64 b, u64 c) {
    u64 d; asm("fma.rn.f32x2 %0, %1, %2, %3;" : "=l"(d) : "l"(a), "l"(b), "l"(c)); return d;
}

__global__ void __launch_bounds__(NTHR, 1)
tpa_kernel(const float* __restrict__ t_g, const float* __restrict__ z_g,
           const float* __restrict__ mask_g,
           const float* __restrict__ wq_g, const float* __restrict__ wk_g,
           const float* __restrict__ wv_g, const float* __restrict__ wo_g,
           const float* __restrict__ bo_g, float* __restrict__ out_g)
{
    extern __shared__ float S[];
    const int tid  = threadIdx.x;
    const int base = blockIdx.x * PT;

    // mask -> bias + output gate
    float bias0, bias1, bias2, bias3, msum;
    {
        float m0 = __ldg(mask_g + 0), m1 = __ldg(mask_g + 1);
        float m2 = __ldg(mask_g + 2), m3 = __ldg(mask_g + 3);
        bias0 = 1e9f*(m0-1.f); bias1 = 1e9f*(m1-1.f);
        bias2 = 1e9f*(m2-1.f); bias3 = 1e9f*(m3-1.f);
        msum = m0+m1+m2+m3;
    }
    const float gate = (msum > 0.f) ? 1.f : 0.f;

    // ---------------- phase 0: staging ----------------
    {
        const float4* src; float4* dst;
        src = (const float4*)wq_g; dst = (float4*)(S + OFF_WQ);
        for (int i = tid; i < 2048; i += NTHR) dst[i] = src[i];
        src = (const float4*)wk_g; dst = (float4*)(S + OFF_WK);
        for (int i = tid; i < 1024; i += NTHR) dst[i] = src[i];
        src = (const float4*)wv_g; dst = (float4*)(S + OFF_WV);
        for (int i = tid; i < 1024; i += NTHR) dst[i] = src[i];
        src = (const float4*)wo_g; dst = (float4*)(S + OFF_WO);
        for (int i = tid; i < 2048; i += NTHR) dst[i] = src[i];
        src = (const float4*)bo_g; dst = (float4*)(S + OFF_BO);
        for (int i = tid; i < 32;   i += NTHR) dst[i] = src[i];

        // Z tile: global [p][128] -> shared transposed ZS[c][p] (row stride 65)
        for (int i = tid; i < 2048; i += NTHR) {
            int p = i >> 5, c4 = i & 31;
            float4 v = *(const float4*)(z_g + (size_t)(base + p) * 128 + c4 * 4);
            S[OFF_ZS + (4*c4+0)*65 + p] = v.x;
            S[OFF_ZS + (4*c4+1)*65 + p] = v.y;
            S[OFF_ZS + (4*c4+2)*65 + p] = v.z;
            S[OFF_ZS + (4*c4+3)*65 + p] = v.w;
        }
        // T tile: global [s][p][c] -> TS4[p][c][s] (p stride 260).
        // Lane split (s: 2b, p_low: 3b) -> STS bank = 4*p_low + s + const:
        // all 32 banks hit exactly once -> conflict-free scatter stores.
        for (int i = tid; i < 4096; i += NTHR) {
            int s  = i & 3, pl = (i >> 2) & 7, c4 = (i >> 5) & 15, ph = i >> 9;
            int p  = ph * 8 + pl;
            float4 v = *(const float4*)(t_g + ((size_t)s << 24) +
                                        (size_t)(base + p) * 64 + c4 * 4);
            float* tr = S + OFF_TS + p*TS_PSTRIDE + c4*16 + s;
            tr[0]  = v.x; tr[4]  = v.y; tr[8]  = v.z; tr[12] = v.w;
        }
    }
    __syncthreads();

    // ------- phase 1: Q = Z @ Wq * 0.25 -> QS[p][o] (stride 66) -------
    // 512 thr: og = tid&31 (one u64 = outputs {2og,2og+1}), pg = tid>>5 (4 px)
    {
        const int og = tid & 31, pg = tid >> 5;
        const int p0 = pg * 4;
        u64 acc[4];
#pragma unroll
        for (int i = 0; i < 4; ++i) acc[i] = 0ull;
#pragma unroll 4
        for (int c = 0; c < 128; ++c) {
            const float* zr = S + OFF_ZS + c*65 + p0;         // warp-broadcast
            u64 w = *(const u64*)(S + OFF_WQ + c*64 + 2*og);  // 8B-stride lanes
#pragma unroll
            for (int i = 0; i < 4; ++i)
                acc[i] = ffma2(pk2(zr[i], zr[i]), w, acc[i]);
        }
#pragma unroll
        for (int i = 0; i < 4; ++i) {
            float a0, a1; upk2(acc[i], a0, a1);
            *(u64*)(S + OFF_QS + (p0 + i)*66 + 2*og) = pk2(a0*0.25f, a1*0.25f);
        }
    }
    __syncthreads();

    // ------- phase 2: attention middle, thread = (half, head, pixel) -------
    {
        const int half = tid >> 8;            // c-range owner: [32*half, 32*half+32)
        const int hp   = tid & 255;
        const int h = hp >> 6, p = hp & 63;

        // load q into regs, then QS region becomes scratch
        const float* qrow = S + OFF_QS + p*66 + h*16;
        u64 q2[8];
#pragma unroll
        for (int j = 0; j < 8; ++j) q2[j] = *(const u64*)(qrow + 2*j);
        __syncthreads();   // all q reads done; QS reusable

        // TS4 row for this pixel: tq[c] = float4{t_s0,t_s1,t_s2,t_s3}(p,c)
        const float4* tq = (const float4*)(S + OFF_TS + p*TS_PSTRIDE) + half*32;
        const float* wkh = S + OFF_WK + h*16 + half*32*64;
        float lg0 = 0.f, lg1 = 0.f, lg2 = 0.f, lg3 = 0.f;
#pragma unroll 2
        for (int c2 = 0; c2 < 32; ++c2) {
            const float* wr = wkh + c2*64;
            u64 a0 = 0ull, a1 = 0ull;
#pragma unroll
            for (int j = 0; j < 8; j += 2) {
                a0 = ffma2(*(const u64*)(wr + 2*j),     q2[j],   a0);
                a1 = ffma2(*(const u64*)(wr + 2*j + 2), q2[j+1], a1);
            }
            float x0, x1, y0, y1; upk2(a0, x0, x1); upk2(a1, y0, y1);
            float qkc = (x0 + x1) + (y0 + y1);
            float4 tv = tq[c2];
            lg0 += qkc * tv.x;
            lg1 += qkc * tv.y;
            lg2 += qkc * tv.z;
            lg3 += qkc * tv.w;
        }
        // combine partial logits through QS region
        float4* pb = (float4*)(S + OFF_QS);
        pb[hp*2 + half] = make_float4(lg0, lg1, lg2, lg3);
        __syncthreads();
        float4 pa = pb[hp*2 + 0];
        float4 pc = pb[hp*2 + 1];
        lg0 = pa.x + pc.x + bias0;  lg1 = pa.y + pc.y + bias1;
        lg2 = pa.z + pc.z + bias2;  lg3 = pa.w + pc.w + bias3;

        float m  = fmaxf(fmaxf(lg0, lg1), fmaxf(lg2, lg3));
        float e0 = __expf(lg0 - m), e1 = __expf(lg1 - m);
        float e2 = __expf(lg2 - m), e3 = __expf(lg3 - m);
        float inv = 1.f / (e0 + e1 + e2 + e3);
        float aw0 = e0*inv, aw1 = e1*inv, aw2 = e2*inv, aw3 = e3*inv;
        __syncthreads();   // partial-logit reads done; QS reusable as OS_b

        u64 oacc[8];
#pragma unroll
        for (int j = 0; j < 8; ++j) oacc[j] = 0ull;
        const float* wvh = S + OFF_WV + h*16 + half*32*64;
#pragma unroll 2
        for (int c2 = 0; c2 < 32; ++c2) {
            float4 tv = tq[c2];
            float tb = aw0*tv.x + aw1*tv.y + aw2*tv.z + aw3*tv.w;
            u64 tb2 = pk2(tb, tb);
            const float* wr = wvh + c2*64;
#pragma unroll
            for (int j = 0; j < 8; ++j)
                oacc[j] = ffma2(tb2, *(const u64*)(wr + 2*j), oacc[j]);
        }
        // half 0 -> OS_a in ZS region; half 1 -> OS_b in QS region (stride 66)
        float* osr = S + (half ? OFF_QS : OFF_ZS) + p*66 + h*16;
#pragma unroll
        for (int j = 0; j < 8; ++j) *(u64*)(osr + 2*j) = oacc[j];
    }
    __syncthreads();

    // ------- phase 3: Out = (OS_a + OS_b) @ Wo + bo, gated -------
    // og = tid&15 (4 u64 = 8 outputs), pg = tid>>4 (2 px)
    {
        const int og = tid & 15, pg = tid >> 4;
        const int p0 = pg * 2;
        u64 acc[2][4];
#pragma unroll
        for (int i = 0; i < 2; ++i)
#pragma unroll
            for (int k = 0; k < 4; ++k) acc[i][k] = 0ull;
#pragma unroll 2
        for (int c = 0; c < 64; ++c) {
            const float* wr = S + OFF_WO + c*128 + 2*og;
            u64 w0 = *(const u64*)(wr);
            u64 w1 = *(const u64*)(wr + 32);
            u64 w2 = *(const u64*)(wr + 64);
            u64 w3 = *(const u64*)(wr + 96);
#pragma unroll
            for (int i = 0; i < 2; ++i) {
                float ov = S[OFF_ZS + (p0+i)*66 + c] + S[OFF_QS + (p0+i)*66 + c];
                u64 od = pk2(ov, ov);
                acc[i][0] = ffma2(od, w0, acc[i][0]);
                acc[i][1] = ffma2(od, w1, acc[i][1]);
                acc[i][2] = ffma2(od, w2, acc[i][2]);
                acc[i][3] = ffma2(od, w3, acc[i][3]);
            }
        }
        const float* bo_s = S + OFF_BO;
#pragma unroll
        for (int i = 0; i < 2; ++i) {
            float* orow = out_g + (size_t)(base + p0 + i) * 128;
#pragma unroll
            for (int k = 0; k < 4; ++k) {
                float r0, r1; upk2(acc[i][k], r0, r1);
                int o = 2*og + 32*k;
                r0 = (r0 + bo_s[o])     * gate;
                r1 = (r1 + bo_s[o + 1]) * gate;
                *(u64*)(orow + o) = pk2(r0, r1);
            }
        }
    }
}

extern "C" void kernel_launch(void* const* d_in, const int* in_sizes, int n_in,
                              void* d_out, int out_size)
{
    (void)in_sizes; (void)n_in; (void)out_size;
    const float* t_g  = (const float*)d_in[0];
    const float* z_g  = (const float*)d_in[1];
    const float* mk_g = (const float*)d_in[2];
    const float* wq_g = (const float*)d_in[3];
    const float* wk_g = (const float*)d_in[4];
    const float* wv_g = (const float*)d_in[5];
    const float* wo_g = (const float*)d_in[6];
    const float* bo_g = (const float*)d_in[7];
    float* out_g = (float*)d_out;

    cudaFuncSetAttribute(tpa_kernel, cudaFuncAttributeMaxDynamicSharedMemorySize,
                         SMEM_FLOATS * (int)sizeof(float));
    tpa_kernel<<<NCTA, NTHR, SMEM_FLOATS * sizeof(float)>>>(
        t_g, z_g, mk_g, wq_g, wk_g, wv_g, wo_g, bo_g, out_g);
}

// round 15
// speedup vs baseline: 1.2109x; 1.0620x over previous
#include <cuda_runtime.h>
#include <cstdint>

// TemplatePointwiseAttention, fully fused, fp32 + packed f32x2 FMA.
// R15 == R10 resubmit (never ran): attack the measured smem-crossbar wall
// (L1=73.7% @ 730us):
//  - ph2: quarter-split c x 2px/thread, 4x broadcast LDS.128 weights from
//    quarter-swizzled WK/WV, shfl-butterfly combine (no smem partials).
//  - ph1: ZS stride 68 -> z loads become one broadcast LDS.128.
//  - ph3: single OS buffer.

typedef unsigned long long u64;

#define NCTA 4096      // (512*512)/64
#define PT   64
#define NTHR 512

#define OFF_ZS 0       // [128][68] z^T (stride 68); reused as OS[64][66]
#define OFF_TS 8704    // TS4[64][64][4], pixel stride 260
#define OFF_QS 25344   // [64][66]
#define OFF_WQ 29568   // [128][64]
#define OFF_WK 37760   // [64][64] + 4-float shift per c-quarter (swizzled)
#define OFF_WV 41920   // same layout
#define OFF_WO 46080   // [64][128]
#define OFF_BO 54272   // [128]
#define SMEM_FLOATS 54400
#define TS_PSTRIDE 260

__device__ __forceinline__ u64 pk2(float lo, float hi) {
    u64 r; asm("mov.b64 %0, {%1, %2};" : "=l"(r) : "f"(lo), "f"(hi)); return r;
}
__device__ __forceinline__ void upk2(u64 v, float& lo, float& hi) {
    asm("mov.b64 {%0, %1}, %2;" : "=f"(lo), "=f"(hi) : "l"(v));
}
__device__ __forceinline__ u64 ffma2(u64 a, u64 b, u64 c) {
    u64 d; asm("fma.rn.f32x2 %0, %1, %2, %3;" : "=l"(d) : "l"(a), "l"(b), "l"(c)); return d;
}

__global__ void __launch_bounds__(NTHR, 1)
tpa_kernel(const float* __restrict__ t_g, const float* __restrict__ z_g,
           const float* __restrict__ mask_g,
           const float* __restrict__ wq_g, const float* __restrict__ wk_g,
           const float* __restrict__ wv_g, const float* __restrict__ wo_g,
           const float* __restrict__ bo_g, float* __restrict__ out_g)
{
    extern __shared__ float S[];
    const int tid  = threadIdx.x;
    const int base = blockIdx.x * PT;

    float bias0, bias1, bias2, bias3, msum;
    {
        float m0 = __ldg(mask_g + 0), m1 = __ldg(mask_g + 1);
        float m2 = __ldg(mask_g + 2), m3 = __ldg(mask_g + 3);
        bias0 = 1e9f*(m0-1.f); bias1 = 1e9f*(m1-1.f);
        bias2 = 1e9f*(m2-1.f); bias3 = 1e9f*(m3-1.f);
        msum = m0+m1+m2+m3;
    }
    const float gate = (msum > 0.f) ? 1.f : 0.f;

    // ---------------- phase 0: staging ----------------
    {
        const float4* src; float4* dst;
        src = (const float4*)wq_g; dst = (float4*)(S + OFF_WQ);
        for (int i = tid; i < 2048; i += NTHR) dst[i] = src[i];
        src = (const float4*)wo_g; dst = (float4*)(S + OFF_WO);
        for (int i = tid; i < 2048; i += NTHR) dst[i] = src[i];
        src = (const float4*)bo_g; dst = (float4*)(S + OFF_BO);
        for (int i = tid; i < 32;   i += NTHR) dst[i] = src[i];

        // WK/WV: row c at base c*64 + 4*(c>>4)  (quarter swizzle)
        for (int i = tid; i < 1024; i += NTHR) {
            int c = i >> 4, k = i & 15;
            int off = c*64 + 4*(c >> 4) + 4*k;
            *(float4*)(S + OFF_WK + off) = ((const float4*)wk_g)[i];
            *(float4*)(S + OFF_WV + off) = ((const float4*)wv_g)[i];
        }

        // Z tile: global [p][128] -> ZS[c][p], stride 68 (p-fastest lanes:
        // STS bank = p + const -> conflict-free)
        for (int i = tid; i < 2048; i += NTHR) {
            int p = i & 63, c4 = i >> 6;
            float4 v = *(const float4*)(z_g + (size_t)(base + p) * 128 + c4 * 4);
            S[OFF_ZS + (4*c4+0)*68 + p] = v.x;
            S[OFF_ZS + (4*c4+1)*68 + p] = v.y;
            S[OFF_ZS + (4*c4+2)*68 + p] = v.z;
            S[OFF_ZS + (4*c4+3)*68 + p] = v.w;
        }
        // T tile: [s][p][c] -> TS4[p][c][s]; lane split (s,p_low) makes the
        // scatter STS hit all 32 banks exactly once.
        for (int i = tid; i < 4096; i += NTHR) {
            int s  = i & 3, pl = (i >> 2) & 7, c4 = (i >> 5) & 15, ph = i >> 9;
            int p  = ph * 8 + pl;
            float4 v = *(const float4*)(t_g + ((size_t)s << 24) +
                                        (size_t)(base + p) * 64 + c4 * 4);
            float* tr = S + OFF_TS + p*TS_PSTRIDE + c4*16 + s;
            tr[0]  = v.x; tr[4]  = v.y; tr[8]  = v.z; tr[12] = v.w;
        }
    }
    __syncthreads();

    // ------- phase 1: Q = Z @ Wq * 0.25 -> QS[p][o] (stride 66) -------
    {
        const int og = tid & 31, pg = tid >> 5;
        const int p0 = pg * 4;
        u64 acc[4];
#pragma unroll
        for (int i = 0; i < 4; ++i) acc[i] = 0ull;
#pragma unroll 4
        for (int c = 0; c < 128; ++c) {
            float4 zv = *(const float4*)(S + OFF_ZS + c*68 + p0);  // broadcast
            u64 w = *(const u64*)(S + OFF_WQ + c*64 + 2*og);
            acc[0] = ffma2(pk2(zv.x, zv.x), w, acc[0]);
            acc[1] = ffma2(pk2(zv.y, zv.y), w, acc[1]);
            acc[2] = ffma2(pk2(zv.z, zv.z), w, acc[2]);
            acc[3] = ffma2(pk2(zv.w, zv.w), w, acc[3]);
        }
#pragma unroll
        for (int i = 0; i < 4; ++i) {
            float a0, a1; upk2(acc[i], a0, a1);
            *(u64*)(S + OFF_QS + (p0 + i)*66 + 2*og) = pk2(a0*0.25f, a1*0.25f);
        }
    }
    __syncthreads();

    // ------- phase 2: thread = (c-quarter q in lane[3:4], head, px-pair) ----
    {
        const int lane = tid & 31, warp = tid >> 5;
        const int q = lane >> 3;
        const int h = warp & 3;
        const int pp = (warp >> 2) * 8 + (lane & 7);
        const int p0 = pp, p1 = pp + 32;
        const int cb = q * 16;

        u64 qA[8], qB[8];
        {
            const float* ra = S + OFF_QS + p0*66 + h*16;
            const float* rb = S + OFF_QS + p1*66 + h*16;
#pragma unroll
            for (int j = 0; j < 8; ++j) {
                qA[j] = *(const u64*)(ra + 2*j);
                qB[j] = *(const u64*)(rb + 2*j);
            }
        }
        const float4* tA = (const float4*)(S + OFF_TS + p0*TS_PSTRIDE) + cb;
        const float4* tB = (const float4*)(S + OFF_TS + p1*TS_PSTRIDE) + cb;
        const float* wkb = S + OFF_WK + cb*64 + 4*q + h*16;
        const float* wvb = S + OFF_WV + cb*64 + 4*q + h*16;

        float lgA0=0.f, lgA1=0.f, lgA2=0.f, lgA3=0.f;
        float lgB0=0.f, lgB1=0.f, lgB2=0.f, lgB3=0.f;
#pragma unroll 2
        for (int c2 = 0; c2 < 16; ++c2) {
            const float* wr = wkb + c2*64;
            float4 f0 = *(const float4*)(wr);
            float4 f1 = *(const float4*)(wr + 4);
            float4 f2 = *(const float4*)(wr + 8);
            float4 f3 = *(const float4*)(wr + 12);
            u64 w0 = pk2(f0.x,f0.y), w1 = pk2(f0.z,f0.w);
            u64 w2 = pk2(f1.x,f1.y), w3 = pk2(f1.z,f1.w);
            u64 w4 = pk2(f2.x,f2.y), w5 = pk2(f2.z,f2.w);
            u64 w6 = pk2(f3.x,f3.y), w7 = pk2(f3.z,f3.w);

            u64 a0 = ffma2(w0,qA[0],0ull), a1 = ffma2(w1,qA[1],0ull);
            a0 = ffma2(w2,qA[2],a0); a1 = ffma2(w3,qA[3],a1);
            a0 = ffma2(w4,qA[4],a0); a1 = ffma2(w5,qA[5],a1);
            a0 = ffma2(w6,qA[6],a0); a1 = ffma2(w7,qA[7],a1);
            u64 b0 = ffma2(w0,qB[0],0ull), b1 = ffma2(w1,qB[1],0ull);
            b0 = ffma2(w2,qB[2],b0); b1 = ffma2(w3,qB[3],b1);
            b0 = ffma2(w4,qB[4],b0); b1 = ffma2(w5,qB[5],b1);
            b0 = ffma2(w6,qB[6],b0); b1 = ffma2(w7,qB[7],b1);

            float x0,x1,y0,y1; upk2(a0,x0,x1); upk2(a1,y0,y1);
            float qkA = (x0+x1)+(y0+y1);
            upk2(b0,x0,x1); upk2(b1,y0,y1);
            float qkB = (x0+x1)+(y0+y1);

            float4 tvA = tA[c2], tvB = tB[c2];
            lgA0 += qkA*tvA.x; lgA1 += qkA*tvA.y;
            lgA2 += qkA*tvA.z; lgA3 += qkA*tvA.w;
            lgB0 += qkB*tvB.x; lgB1 += qkB*tvB.y;
            lgB2 += qkB*tvB.z; lgB3 += qkB*tvB.w;
        }
        // butterfly-combine across the 4 c-quarters (lane xor 8, 16)
        const unsigned FULL = 0xffffffffu;
#define CMB(v) v += __shfl_xor_sync(FULL, v, 8); v += __shfl_xor_sync(FULL, v, 16)
        CMB(lgA0); CMB(lgA1); CMB(lgA2); CMB(lgA3);
        CMB(lgB0); CMB(lgB1); CMB(lgB2); CMB(lgB3);
#undef CMB
        lgA0 += bias0; lgA1 += bias1; lgA2 += bias2; lgA3 += bias3;
        lgB0 += bias0; lgB1 += bias1; lgB2 += bias2; lgB3 += bias3;

        float mA = fmaxf(fmaxf(lgA0,lgA1), fmaxf(lgA2,lgA3));
        float eA0 = __expf(lgA0-mA), eA1 = __expf(lgA1-mA);
        float eA2 = __expf(lgA2-mA), eA3 = __expf(lgA3-mA);
        float ivA = 1.f/(eA0+eA1+eA2+eA3);
        float awA0=eA0*ivA, awA1=eA1*ivA, awA2=eA2*ivA, awA3=eA3*ivA;
        float mB = fmaxf(fmaxf(lgB0,lgB1), fmaxf(lgB2,lgB3));
        float eB0 = __expf(lgB0-mB), eB1 = __expf(lgB1-mB);
        float eB2 = __expf(lgB2-mB), eB3 = __expf(lgB3-mB);
        float ivB = 1.f/(eB0+eB1+eB2+eB3);
        float awB0=eB0*ivB, awB1=eB1*ivB, awB2=eB2*ivB, awB3=eB3*ivB;

        u64 oA[8], oB[8];
#pragma unroll
        for (int j = 0; j < 8; ++j) { oA[j] = 0ull; oB[j] = 0ull; }
#pragma unroll 2
        for (int c2 = 0; c2 < 16; ++c2) {
            const float* wr = wvb + c2*64;
            float4 f0 = *(const float4*)(wr);
            float4 f1 = *(const float4*)(wr + 4);
            float4 f2 = *(const float4*)(wr + 8);
            float4 f3 = *(const float4*)(wr + 12);
            float4 tvA = tA[c2], tvB = tB[c2];
            float tbA = awA0*tvA.x + awA1*tvA.y + awA2*tvA.z + awA3*tvA.w;
            float tbB = awB0*tvB.x + awB1*tvB.y + awB2*tvB.z + awB3*tvB.w;
            u64 ta = pk2(tbA,tbA), tb = pk2(tbB,tbB);
            u64 w0 = pk2(f0.x,f0.y), w1 = pk2(f0.z,f0.w);
            u64 w2 = pk2(f1.x,f1.y), w3 = pk2(f1.z,f1.w);
            u64 w4 = pk2(f2.x,f2.y), w5 = pk2(f2.z,f2.w);
            u64 w6 = pk2(f3.x,f3.y), w7 = pk2(f3.z,f3.w);
            oA[0]=ffma2(ta,w0,oA[0]); oA[1]=ffma2(ta,w1,oA[1]);
            oA[2]=ffma2(ta,w2,oA[2]); oA[3]=ffma2(ta,w3,oA[3]);
            oA[4]=ffma2(ta,w4,oA[4]); oA[5]=ffma2(ta,w5,oA[5]);
            oA[6]=ffma2(ta,w6,oA[6]); oA[7]=ffma2(ta,w7,oA[7]);
            oB[0]=ffma2(tb,w0,oB[0]); oB[1]=ffma2(tb,w1,oB[1]);
            oB[2]=ffma2(tb,w2,oB[2]); oB[3]=ffma2(tb,w3,oB[3]);
            oB[4]=ffma2(tb,w4,oB[4]); oB[5]=ffma2(tb,w5,oB[5]);
            oB[6]=ffma2(tb,w6,oB[6]); oB[7]=ffma2(tb,w7,oB[7]);
        }
        // combine O partials across quarters via shfl, q==0 lanes write OS
#pragma unroll
        for (int j = 0; j < 8; ++j) {
            float lo, hi;
            upk2(oA[j], lo, hi);
            lo += __shfl_xor_sync(FULL, lo, 8);  hi += __shfl_xor_sync(FULL, hi, 8);
            lo += __shfl_xor_sync(FULL, lo, 16); hi += __shfl_xor_sync(FULL, hi, 16);
            oA[j] = pk2(lo, hi);
            upk2(oB[j], lo, hi);
            lo += __shfl_xor_sync(FULL, lo, 8);  hi += __shfl_xor_sync(FULL, hi, 8);
            lo += __shfl_xor_sync(FULL, lo, 16); hi += __shfl_xor_sync(FULL, hi, 16);
            oB[j] = pk2(lo, hi);
        }
        if (q == 0) {
            float* ra = S + OFF_ZS + p0*66 + h*16;
            float* rb = S + OFF_ZS + p1*66 + h*16;
#pragma unroll
            for (int j = 0; j < 8; ++j) {
                *(u64*)(ra + 2*j) = oA[j];
                *(u64*)(rb + 2*j) = oB[j];
            }
        }
    }
    __syncthreads();

    // ------- phase 3: Out = OS @ Wo + bo, gated -------
    {
        const int og = tid & 15, pg = tid >> 4;
        const int p0 = pg * 2;
        u64 acc[2][4];
#pragma unroll
        for (int i = 0; i < 2; ++i)
#pragma unroll
            for (int k = 0; k < 4; ++k) acc[i][k] = 0ull;
#pragma unroll 2
        for (int c = 0; c < 64; ++c) {
            const float* wr = S + OFF_WO + c*128 + 2*og;
            u64 w0 = *(const u64*)(wr);
            u64 w1 = *(const u64*)(wr + 32);
            u64 w2 = *(const u64*)(wr + 64);
            u64 w3 = *(const u64*)(wr + 96);
#pragma unroll
            for (int i = 0; i < 2; ++i) {
                float ov = S[OFF_ZS + (p0+i)*66 + c];
                u64 od = pk2(ov, ov);
                acc[i][0] = ffma2(od, w0, acc[i][0]);
                acc[i][1] = ffma2(od, w1, acc[i][1]);
                acc[i][2] = ffma2(od, w2, acc[i][2]);
                acc[i][3] = ffma2(od, w3, acc[i][3]);
            }
        }
        const float* bo_s = S + OFF_BO;
#pragma unroll
        for (int i = 0; i < 2; ++i) {
            float* orow = out_g + (size_t)(base + p0 + i) * 128;
#pragma unroll
            for (int k = 0; k < 4; ++k) {
                float r0, r1; upk2(acc[i][k], r0, r1);
                int o = 2*og + 32*k;
                r0 = (r0 + bo_s[o])     * gate;
                r1 = (r1 + bo_s[o + 1]) * gate;
                *(u64*)(orow + o) = pk2(r0, r1);
            }
        }
    }
}

extern "C" void kernel_launch(void* const* d_in, const int* in_sizes, int n_in,
                              void* d_out, int out_size)
{
    (void)in_sizes; (void)n_in; (void)out_size;
    const float* t_g  = (const float*)d_in[0];
    const float* z_g  = (const float*)d_in[1];
    const float* mk_g = (const float*)d_in[2];
    const float* wq_g = (const float*)d_in[3];
    const float* wk_g = (const float*)d_in[4];
    const float* wv_g = (const float*)d_in[5];
    const float* wo_g = (const float*)d_in[6];
    const float* bo_g = (const float*)d_in[7];
    float* out_g = (float*)d_out;

    cudaFuncSetAttribute(tpa_kernel, cudaFuncAttributeMaxDynamicSharedMemorySize,
                         SMEM_FLOATS * (int)sizeof(float));
    tpa_kernel<<<NCTA, NTHR, SMEM_FLOATS * sizeof(float)>>>(
        t_g, z_g, mk_g, wq_g, wk_g, wv_g, wo_g, bo_g, out_g);
}